// round 13
// baseline (speedup 1.0000x reference)
#include <cuda_runtime.h>
#include <cstdint>
#include <cstddef>

#define B_ 16
#define C_ 512
#define N_ 4096
#define K_ 32
#define NS_ 8                 // K3 n-splits (512 n each)
#define CT_ 4                 // K3 c-tiles (128 c each)
#define NT_ 32                // K1 n-tiles (128 n each)

// Scratch (device globals — allocation-free rule)
__device__ float g_A[B_ * K_ * N_];                       // [b][k][n] tf32-rounded, 8 MB
__device__ float g_part[B_ * NS_ * CT_ * K_ * 128];       // 8 MB partials
__device__ float g_as[B_ * K_ * NT_];                     // per-ntile Asum partials

__device__ __forceinline__ uint32_t tf32_of(float a) {
    uint32_t r;
    asm("{ .reg .b32 t; cvt.rna.tf32.f32 t, %1; mov.b32 %0, t; }" : "=r"(r) : "f"(a));
    return r;
}
__device__ __forceinline__ void mma16888(float* d, const uint32_t* a, const uint32_t* b) {
    asm volatile(
        "mma.sync.aligned.m16n8k8.row.col.f32.tf32.tf32.f32 "
        "{%0,%1,%2,%3}, {%4,%5,%6,%7}, {%8,%9}, {%0,%1,%2,%3};"
        : "+f"(d[0]), "+f"(d[1]), "+f"(d[2]), "+f"(d[3])
        : "r"(a[0]), "r"(a[1]), "r"(a[2]), "r"(a[3]), "r"(b[0]), "r"(b[1]));
}
__device__ __forceinline__ uint32_t smem_u32(const void* p) {
    uint32_t a;
    asm("{ .reg .u64 t; cvta.to.shared.u64 t, %1; cvt.u32.u64 %0, t; }" : "=r"(a) : "l"(p));
    return a;
}
__device__ __forceinline__ void cpa16(uint32_t dst, const void* src) {
    asm volatile("cp.async.cg.shared.global [%0], [%1], 16;" :: "r"(dst), "l"(src));
}
__device__ __forceinline__ void cpa_commit() {
    asm volatile("cp.async.commit_group;" ::: "memory");
}
__device__ __forceinline__ void cpa_wait1() {
    asm volatile("cp.async.wait_group 1;" ::: "memory");
}
__device__ __forceinline__ void cpa_wait0() {
    asm volatile("cp.async.wait_group 0;" ::: "memory");
}

// =====================================================================
// K1: logits + softmax via mma.sync tf32.
// R13: 16-c chunks (32 chunks), 3-stage cp.async x ring [16c][136n],
// cw [32k][20] double-buffered via regs -> ~32.5 KB static smem,
// __launch_bounds__(256,4) -> 4 CTAs/SM, 512 CTAs = single wave.
// grid (32 n-tiles, 16 b), 256 threads (8 warps, warp owns 16 n).
// =====================================================================
#define XS1 2176   // words per x stage (16*136)

__global__ void __launch_bounds__(256, 4) k1_softmax(const float* __restrict__ x,
                                                     const float* __restrict__ cw,
                                                     const float* __restrict__ scale) {
    __shared__ uint32_t ring[3 * XS1];        // 26112 B (aliased as Ao after)
    __shared__ uint32_t cw_s[2 * 640];        //  5120 B  [32k][20]
    __shared__ float sc_s[K_], c2_s[K_];
    __shared__ float as_s[8 * K_];

    const int tid  = threadIdx.x;
    const int lane = tid & 31, w = tid >> 5;
    const int b    = blockIdx.y;
    const int n0   = blockIdx.x * 128;
    const int ar0  = lane >> 2, an0 = lane & 3;
    const uint32_t smb = smem_u32(ring);

    if (tid < 32) sc_s[tid] = scale[tid];

    // staging maps
    const int xrow = tid >> 4;             // x: c row 0..15
    const int xu   = tid & 15;             // x: unit (16B) index; covers xu and xu+16
    const int kk   = tid >> 3;             // cw: k row
    const int cq   = tid & 7;              // cw: c pair index (2 c each)

    const float* xg  = x  + (size_t)b * C_ * N_ + n0;
    const float* cwg = cw + kk * C_ + cq * 2;

    float c2p = 0.f;
    float sq0 = 0.f, sq1 = 0.f;
    float acc[4][4];
    #pragma unroll
    for (int nt = 0; nt < 4; nt++)
        #pragma unroll
        for (int j = 0; j < 4; j++) acc[nt][j] = 0.f;

    // ---- prologue: async-issue x chunks 0,1; reg-stage cw0; prefetch cw1 ----
    #pragma unroll
    for (int s = 0; s < 2; s++) {
        const uint32_t dstb = smb + s * (XS1 * 4);
        cpa16(dstb + (xrow * 136 + xu * 4) * 4,
              xg + (size_t)(s * 16 + xrow) * N_ + xu * 4);
        cpa16(dstb + (xrow * 136 + (xu + 16) * 4) * 4,
              xg + (size_t)(s * 16 + xrow) * N_ + (xu + 16) * 4);
        cpa_commit();
    }
    float2 cwr = *(const float2*)(cwg);
    {
        uint32_t u0 = tf32_of(cwr.x), u1 = tf32_of(cwr.y);
        float t0 = __uint_as_float(u0), t1 = __uint_as_float(u1);
        c2p += t0 * t0 + t1 * t1;
        cw_s[kk * 20 + cq * 2]     = u0;
        cw_s[kk * 20 + cq * 2 + 1] = u1;
    }
    cwr = *(const float2*)(cwg + 16);
    cpa_wait1();
    __syncthreads();

    // ---- mainloop: 32 chunks of 16 c ----
    for (int ch = 0; ch < 32; ch++) {
        if (ch < 30) {
            const uint32_t dstb = smb + ((ch + 2) % 3) * (XS1 * 4);
            cpa16(dstb + (xrow * 136 + xu * 4) * 4,
                  xg + (size_t)((ch + 2) * 16 + xrow) * N_ + xu * 4);
            cpa16(dstb + (xrow * 136 + (xu + 16) * 4) * 4,
                  xg + (size_t)((ch + 2) * 16 + xrow) * N_ + (xu + 16) * 4);
            cpa_commit();
        }
        if (ch < 31) {
            uint32_t u0 = tf32_of(cwr.x), u1 = tf32_of(cwr.y);
            float t0 = __uint_as_float(u0), t1 = __uint_as_float(u1);
            c2p += t0 * t0 + t1 * t1;
            uint32_t* cd = cw_s + ((ch + 1) & 1) * 640 + kk * 20 + cq * 2;
            cd[0] = u0; cd[1] = u1;
        }
        if (ch < 30) cwr = *(const float2*)(cwg + (ch + 2) * 16);

        const uint32_t* xb   = ring + (ch % 3) * XS1;
        const uint32_t* cb_s = cw_s + (ch & 1) * 640;
        #pragma unroll
        for (int ks = 0; ks < 2; ks++) {
            const int cb = ks * 8;
            const uint32_t* ap = xb + (cb + an0) * 136 + 16 * w + ar0;
            const float f0 = __uint_as_float(ap[0]);
            const float f1 = __uint_as_float(ap[8]);
            const float f2 = __uint_as_float(ap[4 * 136]);
            const float f3 = __uint_as_float(ap[4 * 136 + 8]);
            sq0 += f0 * f0 + f2 * f2;
            sq1 += f1 * f1 + f3 * f3;
            uint32_t af[4];
            af[0] = tf32_of(f0); af[1] = tf32_of(f1);
            af[2] = tf32_of(f2); af[3] = tf32_of(f3);
            #pragma unroll
            for (int nt = 0; nt < 4; nt++) {
                uint32_t bf[2];
                const uint32_t* bp = cb_s + (8 * nt + ar0) * 20 + cb + an0;
                bf[0] = bp[0];
                bf[1] = bp[4];
                mma16888(acc[nt], af, bf);
            }
        }
        if (ch < 30) cpa_wait1(); else cpa_wait0();
        __syncthreads();
    }

    // ---- c2 reduce (8 consecutive lanes per k) ----
    c2p += __shfl_down_sync(0xffffffffu, c2p, 4, 8);
    c2p += __shfl_down_sync(0xffffffffu, c2p, 2, 8);
    c2p += __shfl_down_sync(0xffffffffu, c2p, 1, 8);
    if (cq == 0) c2_s[kk] = c2p;
    __syncthreads();

    // ---- x2 via shfl over the an0 quad (exact fp32) ----
    float x2r0 = sq0, x2r1 = sq1;
    x2r0 += __shfl_xor_sync(0xffffffffu, x2r0, 1);
    x2r0 += __shfl_xor_sync(0xffffffffu, x2r0, 2);
    x2r1 += __shfl_xor_sync(0xffffffffu, x2r1, 1);
    x2r1 += __shfl_xor_sync(0xffffffffu, x2r1, 2);

    // ---- logits + softmax ----
    float lg0[8], lg1[8];
    float m0 = -1e30f, m1 = -1e30f;
    #pragma unroll
    for (int nt = 0; nt < 4; nt++) {
        #pragma unroll
        for (int j = 0; j < 2; j++) {
            const int k = 8 * nt + 2 * an0 + j;
            const float sck = sc_s[k], c2k = c2_s[k];
            float a = sck * (x2r0 - 2.f * acc[nt][j]     + c2k);
            float c = sck * (x2r1 - 2.f * acc[nt][2 + j] + c2k);
            lg0[nt * 2 + j] = a; lg1[nt * 2 + j] = c;
            m0 = fmaxf(m0, a); m1 = fmaxf(m1, c);
        }
    }
    m0 = fmaxf(m0, __shfl_xor_sync(0xffffffffu, m0, 1));
    m0 = fmaxf(m0, __shfl_xor_sync(0xffffffffu, m0, 2));
    m1 = fmaxf(m1, __shfl_xor_sync(0xffffffffu, m1, 1));
    m1 = fmaxf(m1, __shfl_xor_sync(0xffffffffu, m1, 2));
    float s0 = 0.f, s1 = 0.f;
    #pragma unroll
    for (int i = 0; i < 8; i++) {
        lg0[i] = __expf(lg0[i] - m0); s0 += lg0[i];
        lg1[i] = __expf(lg1[i] - m1); s1 += lg1[i];
    }
    s0 += __shfl_xor_sync(0xffffffffu, s0, 1);
    s0 += __shfl_xor_sync(0xffffffffu, s0, 2);
    s1 += __shfl_xor_sync(0xffffffffu, s1, 1);
    s1 += __shfl_xor_sync(0xffffffffu, s1, 2);
    const float inv0 = 1.f / s0, inv1 = 1.f / s1;

    // ---- Asum partials (exact fp32) ----
    float akp[8];
    #pragma unroll
    for (int i = 0; i < 8; i++) akp[i] = lg0[i] * inv0 + lg1[i] * inv1;
    #pragma unroll
    for (int off = 4; off < 32; off <<= 1)
        #pragma unroll
        for (int i = 0; i < 8; i++)
            akp[i] += __shfl_xor_sync(0xffffffffu, akp[i], off);
    if (ar0 == 0) {
        #pragma unroll
        for (int nt = 0; nt < 4; nt++)
            #pragma unroll
            for (int j = 0; j < 2; j++)
                as_s[w * 32 + 8 * nt + 2 * an0 + j] = akp[nt * 2 + j];
    }

    // ---- A (pre-rounded tf32) -> smem transpose (alias ring) -> STG ----
    uint32_t* Ao = ring;                          // [32 k][132 n-pad], 16896 B
    #pragma unroll
    for (int nt = 0; nt < 4; nt++) {
        #pragma unroll
        for (int j = 0; j < 2; j++) {
            const int k = 8 * nt + 2 * an0 + j;
            Ao[k * 132 + 16 * w + ar0]     = tf32_of(lg0[nt * 2 + j] * inv0);
            Ao[k * 132 + 16 * w + ar0 + 8] = tf32_of(lg1[nt * 2 + j] * inv1);
        }
    }
    __syncthreads();
    if (tid < 32) {
        float s = 0.f;
        #pragma unroll
        for (int ww = 0; ww < 8; ww++) s += as_s[ww * 32 + tid];
        g_as[(b * K_ + tid) * NT_ + blockIdx.x] = s;
    }
    float* ag = g_A + (size_t)(b * K_) * N_ + n0;
    #pragma unroll
    for (int t = 0; t < 4; t++) {
        int f = tid + t * 256;                    // 0..1023
        int k = f >> 5, nq = (f & 31) * 4;
        *(uint4*)(ag + (size_t)k * N_ + nq) = *(uint4*)(Ao + k * 132 + nq);
    }
}

// =====================================================================
// K3: enc partial via mma.sync tf32.
// R13: 16-n chunks (32 chunks), 3-stage cp.async x ring [128c][20],
// A [32k][20] double-buffered via regs -> 35.8 KB static smem,
// 4 CTAs/SM, 512 CTAs = single wave.
// D[32k x 128c] += sum_n A[k,n] * x[c,n] over 512 n per CTA.
// =====================================================================
#define XS3 2560   // words per x stage (128*20)

__global__ void __launch_bounds__(256, 4) k3_enc(const float* __restrict__ x) {
    __shared__ uint32_t ring[3 * XS3];        // 30720 B
    __shared__ uint32_t A_s[2 * 640];         //  5120 B  [32k][20]

    const int tid   = threadIdx.x;
    const int lane  = tid & 31, w = tid >> 5;
    const int ctile = blockIdx.x;
    const int ns    = blockIdx.y;
    const int b     = blockIdx.z;
    const int cwarp = w * 16;
    const int ar0   = lane >> 2, an0 = lane & 3;
    const uint32_t smb = smem_u32(ring);

    const float* xg = x   + ((size_t)(b * C_) + ctile * 128) * N_;
    const float* ag = g_A + ((size_t)b * K_) * N_;
    const int nb0 = ns * 512;

    const int xc = tid >> 1;      // c row 0..127 (x stage)
    const int xh = tid & 1;       // n-half (8 n = 2 units)
    const int ak = tid >> 3;      // k row (A stage)
    const int aq = tid & 7;       // n pair (2 n)

    float acc[2][2][4];
    #pragma unroll
    for (int mt = 0; mt < 2; mt++)
        #pragma unroll
        for (int ct = 0; ct < 2; ct++)
            #pragma unroll
            for (int j = 0; j < 4; j++) acc[mt][ct][j] = 0.f;

    // ---- prologue: async-issue x chunks 0,1; reg-stage A0; prefetch A1 ----
    #pragma unroll
    for (int s = 0; s < 2; s++) {
        const int nb = nb0 + s * 16;
        const uint32_t dstb = smb + s * (XS3 * 4);
        cpa16(dstb + (xc * 20 + xh * 8) * 4,     xg + (size_t)xc * N_ + nb + xh * 8);
        cpa16(dstb + (xc * 20 + xh * 8 + 4) * 4, xg + (size_t)xc * N_ + nb + xh * 8 + 4);
        cpa_commit();
    }
    float2 ar = *(const float2*)(ag + (size_t)ak * N_ + nb0 + aq * 2);
    A_s[ak * 20 + aq * 2]     = __float_as_uint(ar.x);   // already tf32 bits
    A_s[ak * 20 + aq * 2 + 1] = __float_as_uint(ar.y);
    ar = *(const float2*)(ag + (size_t)ak * N_ + nb0 + 16 + aq * 2);
    cpa_wait1();
    __syncthreads();

    // ---- mainloop: 32 chunks of 16 n ----
    for (int ch = 0; ch < 32; ch++) {
        if (ch < 30) {
            const int nb = nb0 + (ch + 2) * 16;
            const uint32_t dstb = smb + ((ch + 2) % 3) * (XS3 * 4);
            cpa16(dstb + (xc * 20 + xh * 8) * 4,     xg + (size_t)xc * N_ + nb + xh * 8);
            cpa16(dstb + (xc * 20 + xh * 8 + 4) * 4, xg + (size_t)xc * N_ + nb + xh * 8 + 4);
            cpa_commit();
        }
        if (ch < 31) {
            uint32_t* ad = A_s + ((ch + 1) & 1) * 640 + ak * 20 + aq * 2;
            ad[0] = __float_as_uint(ar.x);
            ad[1] = __float_as_uint(ar.y);
        }
        if (ch < 30)
            ar = *(const float2*)(ag + (size_t)ak * N_ + nb0 + (ch + 2) * 16 + aq * 2);

        const uint32_t* As = A_s + (ch & 1) * 640;
        const uint32_t* Xs = ring + (ch % 3) * XS3;
        #pragma unroll
        for (int ks = 0; ks < 2; ks++) {
            const int nk = ks * 8;
            uint32_t af[2][4], bf[2][2];
            #pragma unroll
            for (int mt = 0; mt < 2; mt++) {
                const uint32_t* ap = As + (mt * 16 + ar0) * 20 + nk + an0;
                af[mt][0] = ap[0];
                af[mt][1] = ap[8 * 20];
                af[mt][2] = ap[4];
                af[mt][3] = ap[8 * 20 + 4];
            }
            #pragma unroll
            for (int ct = 0; ct < 2; ct++) {
                const uint32_t* bp = Xs + (cwarp + ct * 8 + ar0) * 20 + nk + an0;
                bf[ct][0] = tf32_of(__uint_as_float(bp[0]));
                bf[ct][1] = tf32_of(__uint_as_float(bp[4]));
            }
            #pragma unroll
            for (int mt = 0; mt < 2; mt++)
                #pragma unroll
                for (int ct = 0; ct < 2; ct++)
                    mma16888(acc[mt][ct], af[mt], bf[ct]);
        }
        if (ch < 30) cpa_wait1(); else cpa_wait0();
        __syncthreads();
    }

    // ---- epilogue -> g_part[b][ns][ctile][k][c] ----
    float* pb = g_part + (((size_t)(b * NS_ + ns) * CT_ + ctile) << 12);
    const int dr = lane >> 2;
    const int dc = (lane & 3) * 2;
    #pragma unroll
    for (int mt = 0; mt < 2; mt++) {
        #pragma unroll
        for (int ct = 0; ct < 2; ct++) {
            const int c0 = cwarp + ct * 8 + dc;
            const int r0 = mt * 16 + dr;
            *(float2*)(pb + r0 * 128 + c0) =
                make_float2(acc[mt][ct][0], acc[mt][ct][1]);
            *(float2*)(pb + (r0 + 8) * 128 + c0) =
                make_float2(acc[mt][ct][2], acc[mt][ct][3]);
        }
    }
}

// =====================================================================
// K4: per (b,k): Asum from g_as partials + combine + subtract Asum*cw.
// =====================================================================
__global__ void k4_final(float* __restrict__ out, const float* __restrict__ cw) {
    __shared__ float s_asum;
    const int bk  = blockIdx.x;
    const int b   = bk >> 5, k = bk & 31;
    const int tid = threadIdx.x;

    if (tid < 32) {
        float v = g_as[bk * NT_ + tid];
        #pragma unroll
        for (int o = 16; o; o >>= 1) v += __shfl_down_sync(0xffffffffu, v, o);
        if (tid == 0) s_asum = v;
    }
    __syncthreads();
    const float asum = s_asum;

    #pragma unroll
    for (int j = 0; j < 4; j++) {
        const int c  = tid + j * 128;
        const int ct = c >> 7, cl = c & 127;
        float v = 0.f;
        #pragma unroll
        for (int sp = 0; sp < NS_; sp++)
            v += g_part[(((size_t)(b * NS_ + sp) * CT_ + ct) << 12) + k * 128 + cl];
        out[(size_t)bk * C_ + c] = v - asum * cw[k * C_ + c];
    }
}

// =====================================================================
extern "C" void kernel_launch(void* const* d_in, const int* in_sizes, int n_in,
                              void* d_out, int out_size) {
    const float* x     = (const float*)d_in[0];
    const float* cw    = (const float*)d_in[1];
    const float* scale = (const float*)d_in[2];
    float* out = (float*)d_out;

    k1_softmax<<<dim3(NT_, B_), 256>>>(x, cw, scale);
    k3_enc<<<dim3(CT_, NS_, B_), 256>>>(x);
    k4_final<<<B_ * K_, 128>>>(out, cw);
}

// round 14
// speedup vs baseline: 1.0032x; 1.0032x over previous
#include <cuda_runtime.h>
#include <cstdint>
#include <cstddef>

#define B_ 16
#define C_ 512
#define N_ 4096
#define K_ 32
#define NS_ 8                 // K3 n-splits (512 n each)
#define CT_ 4                 // K3 c-tiles (128 c each)
#define NT_ 32                // K1 n-tiles (128 n each)

// Scratch (device globals — allocation-free rule)
__device__ float g_A[B_ * K_ * N_];                       // [b][k][n] tf32-rounded, 8 MB
__device__ float g_part[B_ * NS_ * CT_ * K_ * 128];       // 8 MB partials
__device__ float g_as[B_ * K_ * NT_];                     // per-ntile Asum partials

__device__ __forceinline__ uint32_t tf32_of(float a) {
    uint32_t r;
    asm("{ .reg .b32 t; cvt.rna.tf32.f32 t, %1; mov.b32 %0, t; }" : "=r"(r) : "f"(a));
    return r;
}
__device__ __forceinline__ void mma16888(float* d, const uint32_t* a, const uint32_t* b) {
    asm volatile(
        "mma.sync.aligned.m16n8k8.row.col.f32.tf32.tf32.f32 "
        "{%0,%1,%2,%3}, {%4,%5,%6,%7}, {%8,%9}, {%0,%1,%2,%3};"
        : "+f"(d[0]), "+f"(d[1]), "+f"(d[2]), "+f"(d[3])
        : "r"(a[0]), "r"(a[1]), "r"(a[2]), "r"(a[3]), "r"(b[0]), "r"(b[1]));
}
__device__ __forceinline__ uint32_t smem_u32(const void* p) {
    uint32_t a;
    asm("{ .reg .u64 t; cvta.to.shared.u64 t, %1; cvt.u32.u64 %0, t; }" : "=r"(a) : "l"(p));
    return a;
}
__device__ __forceinline__ void cpa16(uint32_t dst, const void* src) {
    asm volatile("cp.async.cg.shared.global [%0], [%1], 16;" :: "r"(dst), "l"(src));
}
__device__ __forceinline__ void cpa_commit() {
    asm volatile("cp.async.commit_group;" ::: "memory");
}
__device__ __forceinline__ void cpa_wait0() {
    asm volatile("cp.async.wait_group 0;" ::: "memory");
}

// =====================================================================
// K1: logits + softmax via mma.sync tf32.
// R14: 32-c chunks (16 iters, R12 geometry), 2-stage cp.async x ring
// -> 44.3 KB static smem, __launch_bounds__(256,4) -> 4 CTAs/SM,
// depth-1 per-CTA prefetch hidden by cross-CTA warps.
// grid (32 n-tiles, 16 b), 256 threads (8 warps, warp owns 16 n).
// =====================================================================
#define XS1 4352   // words per x stage (32 rows * 136)

__global__ void __launch_bounds__(256, 4) k1_softmax(const float* __restrict__ x,
                                                     const float* __restrict__ cw,
                                                     const float* __restrict__ scale) {
    __shared__ uint32_t ring[2 * XS1];        // 34816 B (aliased as Ao after)
    __shared__ uint32_t cw_s[2 * 1152];       //  9216 B  [32k][36]
    __shared__ float sc_s[K_], c2_s[K_];
    __shared__ float as_s[8 * K_];

    const int tid  = threadIdx.x;
    const int lane = tid & 31, w = tid >> 5;
    const int b    = blockIdx.y;
    const int n0   = blockIdx.x * 128;
    const int ar0  = lane >> 2, an0 = lane & 3;
    const uint32_t smb = smem_u32(ring);

    if (tid < 32) sc_s[tid] = scale[tid];

    // staging maps (R12)
    const int cst = tid >> 5;              // x: c sub-row 0..7 (rows cst+8j)
    const int nq4 = lane * 4;              // x: n offset
    const int kk  = tid >> 3;              // cw: k row
    const int cq  = tid & 7;               // cw: col quad

    const float* xg  = x  + (size_t)b * C_ * N_ + n0;
    const float* cwg = cw + kk * C_ + cq * 4;

    float c2p = 0.f;
    float sq0 = 0.f, sq1 = 0.f;
    float acc[4][4];
    #pragma unroll
    for (int nt = 0; nt < 4; nt++)
        #pragma unroll
        for (int j = 0; j < 4; j++) acc[nt][j] = 0.f;

    // ---- prologue: issue x chunk 0; stage cw0; prefetch cw1 ----
    #pragma unroll
    for (int j = 0; j < 4; j++)
        cpa16(smb + ((cst + 8 * j) * 136 + nq4) * 4,
              xg + (size_t)(cst + 8 * j) * N_ + nq4);
    cpa_commit();
    float4 cwr = *(const float4*)(cwg);
    {
        uint4 u = make_uint4(tf32_of(cwr.x), tf32_of(cwr.y), tf32_of(cwr.z), tf32_of(cwr.w));
        float t0 = __uint_as_float(u.x), t1 = __uint_as_float(u.y);
        float t2 = __uint_as_float(u.z), t3 = __uint_as_float(u.w);
        c2p += t0 * t0 + t1 * t1 + t2 * t2 + t3 * t3;
        *(uint4*)(cw_s + kk * 36 + cq * 4) = u;
    }
    cwr = *(const float4*)(cwg + 32);
    cpa_wait0();
    __syncthreads();

    // ---- mainloop: 16 chunks of 32 c ----
    for (int ch = 0; ch < 16; ch++) {
        // issue x chunk ch+1 into ring[(ch+1)&1] (that buf's compute done at ch-1 sync)
        if (ch < 15) {
            const uint32_t dstb = smb + ((ch + 1) & 1) * (XS1 * 4);
            #pragma unroll
            for (int j = 0; j < 4; j++)
                cpa16(dstb + ((cst + 8 * j) * 136 + nq4) * 4,
                      xg + (size_t)((ch + 1) * 32 + cst + 8 * j) * N_ + nq4);
            cpa_commit();
            // stage cw ch+1 from regs
            uint4 u = make_uint4(tf32_of(cwr.x), tf32_of(cwr.y),
                                 tf32_of(cwr.z), tf32_of(cwr.w));
            float t0 = __uint_as_float(u.x), t1 = __uint_as_float(u.y);
            float t2 = __uint_as_float(u.z), t3 = __uint_as_float(u.w);
            c2p += t0 * t0 + t1 * t1 + t2 * t2 + t3 * t3;
            *(uint4*)(cw_s + ((ch + 1) & 1) * 1152 + kk * 36 + cq * 4) = u;
        }
        if (ch < 14) cwr = *(const float4*)(cwg + (ch + 2) * 32);

        // compute chunk ch
        const uint32_t* xb   = ring + (ch & 1) * XS1;
        const uint32_t* cb_s = cw_s + (ch & 1) * 1152;
        #pragma unroll
        for (int ks = 0; ks < 4; ks++) {
            const int cb = ks * 8;
            const uint32_t* ap = xb + (cb + an0) * 136 + 16 * w + ar0;
            const float f0 = __uint_as_float(ap[0]);
            const float f1 = __uint_as_float(ap[8]);
            const float f2 = __uint_as_float(ap[4 * 136]);
            const float f3 = __uint_as_float(ap[4 * 136 + 8]);
            sq0 += f0 * f0 + f2 * f2;
            sq1 += f1 * f1 + f3 * f3;
            uint32_t af[4];
            af[0] = tf32_of(f0); af[1] = tf32_of(f1);
            af[2] = tf32_of(f2); af[3] = tf32_of(f3);
            #pragma unroll
            for (int nt = 0; nt < 4; nt++) {
                uint32_t bf[2];
                const uint32_t* bp = cb_s + (8 * nt + ar0) * 36 + cb + an0;
                bf[0] = bp[0];
                bf[1] = bp[4];
                mma16888(acc[nt], af, bf);
            }
        }
        if (ch < 15) cpa_wait0();
        __syncthreads();
    }

    // ---- c2 reduce (8 consecutive lanes per k) ----
    c2p += __shfl_down_sync(0xffffffffu, c2p, 4, 8);
    c2p += __shfl_down_sync(0xffffffffu, c2p, 2, 8);
    c2p += __shfl_down_sync(0xffffffffu, c2p, 1, 8);
    if (cq == 0) c2_s[kk] = c2p;
    __syncthreads();

    // ---- x2 via shfl over the an0 quad (exact fp32) ----
    float x2r0 = sq0, x2r1 = sq1;
    x2r0 += __shfl_xor_sync(0xffffffffu, x2r0, 1);
    x2r0 += __shfl_xor_sync(0xffffffffu, x2r0, 2);
    x2r1 += __shfl_xor_sync(0xffffffffu, x2r1, 1);
    x2r1 += __shfl_xor_sync(0xffffffffu, x2r1, 2);

    // ---- logits + softmax ----
    float lg0[8], lg1[8];
    float m0 = -1e30f, m1 = -1e30f;
    #pragma unroll
    for (int nt = 0; nt < 4; nt++) {
        #pragma unroll
        for (int j = 0; j < 2; j++) {
            const int k = 8 * nt + 2 * an0 + j;
            const float sck = sc_s[k], c2k = c2_s[k];
            float a = sck * (x2r0 - 2.f * acc[nt][j]     + c2k);
            float c = sck * (x2r1 - 2.f * acc[nt][2 + j] + c2k);
            lg0[nt * 2 + j] = a; lg1[nt * 2 + j] = c;
            m0 = fmaxf(m0, a); m1 = fmaxf(m1, c);
        }
    }
    m0 = fmaxf(m0, __shfl_xor_sync(0xffffffffu, m0, 1));
    m0 = fmaxf(m0, __shfl_xor_sync(0xffffffffu, m0, 2));
    m1 = fmaxf(m1, __shfl_xor_sync(0xffffffffu, m1, 1));
    m1 = fmaxf(m1, __shfl_xor_sync(0xffffffffu, m1, 2));
    float s0 = 0.f, s1 = 0.f;
    #pragma unroll
    for (int i = 0; i < 8; i++) {
        lg0[i] = __expf(lg0[i] - m0); s0 += lg0[i];
        lg1[i] = __expf(lg1[i] - m1); s1 += lg1[i];
    }
    s0 += __shfl_xor_sync(0xffffffffu, s0, 1);
    s0 += __shfl_xor_sync(0xffffffffu, s0, 2);
    s1 += __shfl_xor_sync(0xffffffffu, s1, 1);
    s1 += __shfl_xor_sync(0xffffffffu, s1, 2);
    const float inv0 = 1.f / s0, inv1 = 1.f / s1;

    // ---- Asum partials (exact fp32) ----
    float akp[8];
    #pragma unroll
    for (int i = 0; i < 8; i++) akp[i] = lg0[i] * inv0 + lg1[i] * inv1;
    #pragma unroll
    for (int off = 4; off < 32; off <<= 1)
        #pragma unroll
        for (int i = 0; i < 8; i++)
            akp[i] += __shfl_xor_sync(0xffffffffu, akp[i], off);
    if (ar0 == 0) {
        #pragma unroll
        for (int nt = 0; nt < 4; nt++)
            #pragma unroll
            for (int j = 0; j < 2; j++)
                as_s[w * 32 + 8 * nt + 2 * an0 + j] = akp[nt * 2 + j];
    }

    // ---- A (pre-rounded tf32) -> smem transpose (alias ring) -> STG ----
    uint32_t* Ao = ring;                          // [32 k][132 n-pad], 16896 B
    #pragma unroll
    for (int nt = 0; nt < 4; nt++) {
        #pragma unroll
        for (int j = 0; j < 2; j++) {
            const int k = 8 * nt + 2 * an0 + j;
            Ao[k * 132 + 16 * w + ar0]     = tf32_of(lg0[nt * 2 + j] * inv0);
            Ao[k * 132 + 16 * w + ar0 + 8] = tf32_of(lg1[nt * 2 + j] * inv1);
        }
    }
    __syncthreads();
    if (tid < 32) {
        float s = 0.f;
        #pragma unroll
        for (int ww = 0; ww < 8; ww++) s += as_s[ww * 32 + tid];
        g_as[(b * K_ + tid) * NT_ + blockIdx.x] = s;
    }
    float* ag = g_A + (size_t)(b * K_) * N_ + n0;
    #pragma unroll
    for (int t = 0; t < 4; t++) {
        int f = tid + t * 256;                    // 0..1023
        int k = f >> 5, nq = (f & 31) * 4;
        *(uint4*)(ag + (size_t)k * N_ + nq) = *(uint4*)(Ao + k * 132 + nq);
    }
}

// =====================================================================
// K3: enc partial via mma.sync tf32.
// R14: 32-n chunks (16 iters, R12 geometry), 2-stage cp.async rings
// for x and A -> 46 KB static smem, 4 CTAs/SM.
// D[32k x 128c] += sum_n A[k,n] * x[c,n] over 512 n per CTA.
// =====================================================================
#define XS3 4608   // words per x stage (128 rows * 36)

__global__ void __launch_bounds__(256, 4) k3_enc(const float* __restrict__ x) {
    __shared__ uint32_t ring[2 * XS3];        // 36864 B
    __shared__ uint32_t A_s[2 * 1152];        //  9216 B  [32k][36]

    const int tid   = threadIdx.x;
    const int lane  = tid & 31, w = tid >> 5;
    const int ctile = blockIdx.x;
    const int ns    = blockIdx.y;
    const int b     = blockIdx.z;
    const int cwarp = w * 16;
    const int ar0   = lane >> 2, an0 = lane & 3;
    const uint32_t smb  = smem_u32(ring);
    const uint32_t smba = smem_u32(A_s);

    const float* xg = x   + ((size_t)(b * C_) + ctile * 128) * N_;
    const float* ag = g_A + ((size_t)b * K_) * N_;
    const int nb0 = ns * 512;

    const int xc = tid >> 1;      // c row 0..127 (x stage)
    const int xh = tid & 1;       // n-half (16 n = 4 units)
    const int ak = tid >> 3;      // k row (A stage)
    const int aq = tid & 7;       // n quad

    float acc[2][2][4];
    #pragma unroll
    for (int mt = 0; mt < 2; mt++)
        #pragma unroll
        for (int ct = 0; ct < 2; ct++)
            #pragma unroll
            for (int j = 0; j < 4; j++) acc[mt][ct][j] = 0.f;

    // ---- prologue: issue chunk 0 (x and A) ----
    #pragma unroll
    for (int j = 0; j < 4; j++)
        cpa16(smb + (xc * 36 + xh * 16 + 4 * j) * 4,
              xg + (size_t)xc * N_ + nb0 + xh * 16 + 4 * j);
    cpa16(smba + (ak * 36 + aq * 4) * 4,
          ag + (size_t)ak * N_ + nb0 + aq * 4);
    cpa_commit();
    cpa_wait0();
    __syncthreads();

    // ---- mainloop: 16 chunks of 32 n ----
    for (int ch = 0; ch < 16; ch++) {
        if (ch < 15) {
            const int nb = nb0 + (ch + 1) * 32;
            const int st = (ch + 1) & 1;
            const uint32_t xdst = smb + st * (XS3 * 4);
            #pragma unroll
            for (int j = 0; j < 4; j++)
                cpa16(xdst + (xc * 36 + xh * 16 + 4 * j) * 4,
                      xg + (size_t)xc * N_ + nb + xh * 16 + 4 * j);
            cpa16(smba + st * 4608 + (ak * 36 + aq * 4) * 4,
                  ag + (size_t)ak * N_ + nb + aq * 4);
            cpa_commit();
        }
        const uint32_t* As = A_s  + (ch & 1) * 1152;
        const uint32_t* Xs = ring + (ch & 1) * XS3;
        #pragma unroll
        for (int ks = 0; ks < 4; ks++) {
            const int nk = ks * 8;
            uint32_t af[2][4], bf[2][2];
            #pragma unroll
            for (int mt = 0; mt < 2; mt++) {
                const uint32_t* ap = As + (mt * 16 + ar0) * 36 + nk + an0;
                af[mt][0] = ap[0];                 // already tf32 bits
                af[mt][1] = ap[8 * 36];
                af[mt][2] = ap[4];
                af[mt][3] = ap[8 * 36 + 4];
            }
            #pragma unroll
            for (int ct = 0; ct < 2; ct++) {
                const uint32_t* bp = Xs + (cwarp + ct * 8 + ar0) * 36 + nk + an0;
                bf[ct][0] = tf32_of(__uint_as_float(bp[0]));
                bf[ct][1] = tf32_of(__uint_as_float(bp[4]));
            }
            #pragma unroll
            for (int mt = 0; mt < 2; mt++)
                #pragma unroll
                for (int ct = 0; ct < 2; ct++)
                    mma16888(acc[mt][ct], af[mt], bf[ct]);
        }
        if (ch < 15) cpa_wait0();
        __syncthreads();
    }

    // ---- epilogue -> g_part[b][ns][ctile][k][c] ----
    float* pb = g_part + (((size_t)(b * NS_ + ns) * CT_ + ctile) << 12);
    const int dr = lane >> 2;
    const int dc = (lane & 3) * 2;
    #pragma unroll
    for (int mt = 0; mt < 2; mt++) {
        #pragma unroll
        for (int ct = 0; ct < 2; ct++) {
            const int c0 = cwarp + ct * 8 + dc;
            const int r0 = mt * 16 + dr;
            *(float2*)(pb + r0 * 128 + c0) =
                make_float2(acc[mt][ct][0], acc[mt][ct][1]);
            *(float2*)(pb + (r0 + 8) * 128 + c0) =
                make_float2(acc[mt][ct][2], acc[mt][ct][3]);
        }
    }
}

// =====================================================================
// K4: per (b,k): Asum from g_as partials + combine + subtract Asum*cw.
// =====================================================================
__global__ void k4_final(float* __restrict__ out, const float* __restrict__ cw) {
    __shared__ float s_asum;
    const int bk  = blockIdx.x;
    const int b   = bk >> 5, k = bk & 31;
    const int tid = threadIdx.x;

    if (tid < 32) {
        float v = g_as[bk * NT_ + tid];
        #pragma unroll
        for (int o = 16; o; o >>= 1) v += __shfl_down_sync(0xffffffffu, v, o);
        if (tid == 0) s_asum = v;
    }
    __syncthreads();
    const float asum = s_asum;

    #pragma unroll
    for (int j = 0; j < 4; j++) {
        const int c  = tid + j * 128;
        const int ct = c >> 7, cl = c & 127;
        float v = 0.f;
        #pragma unroll
        for (int sp = 0; sp < NS_; sp++)
            v += g_part[(((size_t)(b * NS_ + sp) * CT_ + ct) << 12) + k * 128 + cl];
        out[(size_t)bk * C_ + c] = v - asum * cw[k * C_ + c];
    }
}

// =====================================================================
extern "C" void kernel_launch(void* const* d_in, const int* in_sizes, int n_in,
                              void* d_out, int out_size) {
    const float* x     = (const float*)d_in[0];
    const float* cw    = (const float*)d_in[1];
    const float* scale = (const float*)d_in[2];
    float* out = (float*)d_out;

    k1_softmax<<<dim3(NT_, B_), 256>>>(x, cw, scale);
    k3_enc<<<dim3(CT_, NS_, B_), 256>>>(x);
    k4_final<<<B_ * K_, 128>>>(out, cw);
}

// round 15
// speedup vs baseline: 1.0298x; 1.0266x over previous
#include <cuda_runtime.h>
#include <cstdint>
#include <cstddef>

#define B_ 16
#define C_ 512
#define N_ 4096
#define K_ 32
#define NS_ 8                 // K3 n-splits (512 n each)
#define CT_ 4                 // K3 c-tiles (128 c each)
#define NT_ 32                // K1 n-tiles (128 n each)

// Scratch (device globals — allocation-free rule)
__device__ float g_A[B_ * K_ * N_];                       // [b][k][n] tf32-rounded, 8 MB
__device__ float g_part[B_ * NS_ * CT_ * K_ * 128];       // 8 MB partials
__device__ float g_as[B_ * K_ * NT_];                     // per-ntile Asum partials

__device__ __forceinline__ uint32_t tf32_of(float a) {
    uint32_t r;
    asm("{ .reg .b32 t; cvt.rna.tf32.f32 t, %1; mov.b32 %0, t; }" : "=r"(r) : "f"(a));
    return r;
}
__device__ __forceinline__ void mma16888(float* d, const uint32_t* a, const uint32_t* b) {
    asm volatile(
        "mma.sync.aligned.m16n8k8.row.col.f32.tf32.tf32.f32 "
        "{%0,%1,%2,%3}, {%4,%5,%6,%7}, {%8,%9}, {%0,%1,%2,%3};"
        : "+f"(d[0]), "+f"(d[1]), "+f"(d[2]), "+f"(d[3])
        : "r"(a[0]), "r"(a[1]), "r"(a[2]), "r"(a[3]), "r"(b[0]), "r"(b[1]));
}
__device__ __forceinline__ uint32_t smem_u32(const void* p) {
    uint32_t a;
    asm("{ .reg .u64 t; cvta.to.shared.u64 t, %1; cvt.u32.u64 %0, t; }" : "=r"(a) : "l"(p));
    return a;
}
__device__ __forceinline__ void cpa16(uint32_t dst, const void* src) {
    asm volatile("cp.async.cg.shared.global [%0], [%1], 16;" :: "r"(dst), "l"(src));
}
__device__ __forceinline__ void cpa_commit() {
    asm volatile("cp.async.commit_group;" ::: "memory");
}
__device__ __forceinline__ void cpa_wait1() {
    asm volatile("cp.async.wait_group 1;" ::: "memory");
}
__device__ __forceinline__ void cpa_wait0() {
    asm volatile("cp.async.wait_group 0;" ::: "memory");
}

// =====================================================================
// K1: logits + softmax via mma.sync tf32.  (R14 config — measured 31.1us)
// 32-c chunks (16 iters), 2-stage cp.async x ring, 4 CTAs/SM.
// grid (32 n-tiles, 16 b), 256 threads (8 warps, warp owns 16 n).
// =====================================================================
#define XS1 4352   // words per x stage (32 rows * 136)

__global__ void __launch_bounds__(256, 4) k1_softmax(const float* __restrict__ x,
                                                     const float* __restrict__ cw,
                                                     const float* __restrict__ scale) {
    __shared__ uint32_t ring[2 * XS1];        // 34816 B (aliased as Ao after)
    __shared__ uint32_t cw_s[2 * 1152];       //  9216 B  [32k][36]
    __shared__ float sc_s[K_], c2_s[K_];
    __shared__ float as_s[8 * K_];

    const int tid  = threadIdx.x;
    const int lane = tid & 31, w = tid >> 5;
    const int b    = blockIdx.y;
    const int n0   = blockIdx.x * 128;
    const int ar0  = lane >> 2, an0 = lane & 3;
    const uint32_t smb = smem_u32(ring);

    if (tid < 32) sc_s[tid] = scale[tid];

    const int cst = tid >> 5;              // x: c sub-row 0..7 (rows cst+8j)
    const int nq4 = lane * 4;              // x: n offset
    const int kk  = tid >> 3;              // cw: k row
    const int cq  = tid & 7;               // cw: col quad

    const float* xg  = x  + (size_t)b * C_ * N_ + n0;
    const float* cwg = cw + kk * C_ + cq * 4;

    float c2p = 0.f;
    float sq0 = 0.f, sq1 = 0.f;
    float acc[4][4];
    #pragma unroll
    for (int nt = 0; nt < 4; nt++)
        #pragma unroll
        for (int j = 0; j < 4; j++) acc[nt][j] = 0.f;

    // ---- prologue ----
    #pragma unroll
    for (int j = 0; j < 4; j++)
        cpa16(smb + ((cst + 8 * j) * 136 + nq4) * 4,
              xg + (size_t)(cst + 8 * j) * N_ + nq4);
    cpa_commit();
    float4 cwr = *(const float4*)(cwg);
    {
        uint4 u = make_uint4(tf32_of(cwr.x), tf32_of(cwr.y), tf32_of(cwr.z), tf32_of(cwr.w));
        float t0 = __uint_as_float(u.x), t1 = __uint_as_float(u.y);
        float t2 = __uint_as_float(u.z), t3 = __uint_as_float(u.w);
        c2p += t0 * t0 + t1 * t1 + t2 * t2 + t3 * t3;
        *(uint4*)(cw_s + kk * 36 + cq * 4) = u;
    }
    cwr = *(const float4*)(cwg + 32);
    cpa_wait0();
    __syncthreads();

    // ---- mainloop: 16 chunks of 32 c ----
    for (int ch = 0; ch < 16; ch++) {
        if (ch < 15) {
            const uint32_t dstb = smb + ((ch + 1) & 1) * (XS1 * 4);
            #pragma unroll
            for (int j = 0; j < 4; j++)
                cpa16(dstb + ((cst + 8 * j) * 136 + nq4) * 4,
                      xg + (size_t)((ch + 1) * 32 + cst + 8 * j) * N_ + nq4);
            cpa_commit();
            uint4 u = make_uint4(tf32_of(cwr.x), tf32_of(cwr.y),
                                 tf32_of(cwr.z), tf32_of(cwr.w));
            float t0 = __uint_as_float(u.x), t1 = __uint_as_float(u.y);
            float t2 = __uint_as_float(u.z), t3 = __uint_as_float(u.w);
            c2p += t0 * t0 + t1 * t1 + t2 * t2 + t3 * t3;
            *(uint4*)(cw_s + ((ch + 1) & 1) * 1152 + kk * 36 + cq * 4) = u;
        }
        if (ch < 14) cwr = *(const float4*)(cwg + (ch + 2) * 32);

        const uint32_t* xb   = ring + (ch & 1) * XS1;
        const uint32_t* cb_s = cw_s + (ch & 1) * 1152;
        #pragma unroll
        for (int ks = 0; ks < 4; ks++) {
            const int cb = ks * 8;
            const uint32_t* ap = xb + (cb + an0) * 136 + 16 * w + ar0;
            const float f0 = __uint_as_float(ap[0]);
            const float f1 = __uint_as_float(ap[8]);
            const float f2 = __uint_as_float(ap[4 * 136]);
            const float f3 = __uint_as_float(ap[4 * 136 + 8]);
            sq0 += f0 * f0 + f2 * f2;
            sq1 += f1 * f1 + f3 * f3;
            uint32_t af[4];
            af[0] = tf32_of(f0); af[1] = tf32_of(f1);
            af[2] = tf32_of(f2); af[3] = tf32_of(f3);
            #pragma unroll
            for (int nt = 0; nt < 4; nt++) {
                uint32_t bf[2];
                const uint32_t* bp = cb_s + (8 * nt + ar0) * 36 + cb + an0;
                bf[0] = bp[0];
                bf[1] = bp[4];
                mma16888(acc[nt], af, bf);
            }
        }
        if (ch < 15) cpa_wait0();
        __syncthreads();
    }

    // ---- c2 reduce ----
    c2p += __shfl_down_sync(0xffffffffu, c2p, 4, 8);
    c2p += __shfl_down_sync(0xffffffffu, c2p, 2, 8);
    c2p += __shfl_down_sync(0xffffffffu, c2p, 1, 8);
    if (cq == 0) c2_s[kk] = c2p;
    __syncthreads();

    // ---- x2 via shfl over the an0 quad (exact fp32) ----
    float x2r0 = sq0, x2r1 = sq1;
    x2r0 += __shfl_xor_sync(0xffffffffu, x2r0, 1);
    x2r0 += __shfl_xor_sync(0xffffffffu, x2r0, 2);
    x2r1 += __shfl_xor_sync(0xffffffffu, x2r1, 1);
    x2r1 += __shfl_xor_sync(0xffffffffu, x2r1, 2);

    // ---- logits + softmax ----
    float lg0[8], lg1[8];
    float m0 = -1e30f, m1 = -1e30f;
    #pragma unroll
    for (int nt = 0; nt < 4; nt++) {
        #pragma unroll
        for (int j = 0; j < 2; j++) {
            const int k = 8 * nt + 2 * an0 + j;
            const float sck = sc_s[k], c2k = c2_s[k];
            float a = sck * (x2r0 - 2.f * acc[nt][j]     + c2k);
            float c = sck * (x2r1 - 2.f * acc[nt][2 + j] + c2k);
            lg0[nt * 2 + j] = a; lg1[nt * 2 + j] = c;
            m0 = fmaxf(m0, a); m1 = fmaxf(m1, c);
        }
    }
    m0 = fmaxf(m0, __shfl_xor_sync(0xffffffffu, m0, 1));
    m0 = fmaxf(m0, __shfl_xor_sync(0xffffffffu, m0, 2));
    m1 = fmaxf(m1, __shfl_xor_sync(0xffffffffu, m1, 1));
    m1 = fmaxf(m1, __shfl_xor_sync(0xffffffffu, m1, 2));
    float s0 = 0.f, s1 = 0.f;
    #pragma unroll
    for (int i = 0; i < 8; i++) {
        lg0[i] = __expf(lg0[i] - m0); s0 += lg0[i];
        lg1[i] = __expf(lg1[i] - m1); s1 += lg1[i];
    }
    s0 += __shfl_xor_sync(0xffffffffu, s0, 1);
    s0 += __shfl_xor_sync(0xffffffffu, s0, 2);
    s1 += __shfl_xor_sync(0xffffffffu, s1, 1);
    s1 += __shfl_xor_sync(0xffffffffu, s1, 2);
    const float inv0 = 1.f / s0, inv1 = 1.f / s1;

    // ---- Asum partials (exact fp32) ----
    float akp[8];
    #pragma unroll
    for (int i = 0; i < 8; i++) akp[i] = lg0[i] * inv0 + lg1[i] * inv1;
    #pragma unroll
    for (int off = 4; off < 32; off <<= 1)
        #pragma unroll
        for (int i = 0; i < 8; i++)
            akp[i] += __shfl_xor_sync(0xffffffffu, akp[i], off);
    if (ar0 == 0) {
        #pragma unroll
        for (int nt = 0; nt < 4; nt++)
            #pragma unroll
            for (int j = 0; j < 2; j++)
                as_s[w * 32 + 8 * nt + 2 * an0 + j] = akp[nt * 2 + j];
    }

    // ---- A (pre-rounded tf32) -> smem transpose (alias ring) -> STG ----
    uint32_t* Ao = ring;                          // [32 k][132 n-pad]
    #pragma unroll
    for (int nt = 0; nt < 4; nt++) {
        #pragma unroll
        for (int j = 0; j < 2; j++) {
            const int k = 8 * nt + 2 * an0 + j;
            Ao[k * 132 + 16 * w + ar0]     = tf32_of(lg0[nt * 2 + j] * inv0);
            Ao[k * 132 + 16 * w + ar0 + 8] = tf32_of(lg1[nt * 2 + j] * inv1);
        }
    }
    __syncthreads();
    if (tid < 32) {
        float s = 0.f;
        #pragma unroll
        for (int ww = 0; ww < 8; ww++) s += as_s[ww * 32 + tid];
        g_as[(b * K_ + tid) * NT_ + blockIdx.x] = s;
    }
    float* ag = g_A + (size_t)(b * K_) * N_ + n0;
    #pragma unroll
    for (int t = 0; t < 4; t++) {
        int f = tid + t * 256;                    // 0..1023
        int k = f >> 5, nq = (f & 31) * 4;
        *(uint4*)(ag + (size_t)k * N_ + nq) = *(uint4*)(Ao + k * 132 + nq);
    }
}

// =====================================================================
// K3: enc partial via mma.sync tf32.  (R12 config — measured ~41us)
// 32-n chunks (16 iters), 3-stage cp.async rings for x and A,
// dyn smem 69120 B -> 3 CTAs/SM, depth-2 prefetch.
// D[32k x 128c] += sum_n A[k,n] * x[c,n] over 512 n per CTA.
// =====================================================================
#define K3_SMEM 69120

__global__ void __launch_bounds__(256) k3_enc(const float* __restrict__ x) {
    extern __shared__ char sm[];
    const uint32_t smb = smem_u32(sm);

    const int tid   = threadIdx.x;
    const int lane  = tid & 31, w = tid >> 5;
    const int ctile = blockIdx.x;
    const int ns    = blockIdx.y;
    const int b     = blockIdx.z;
    const int cwarp = w * 16;
    const int ar0   = lane >> 2, an0 = lane & 3;

    const float* xg = x   + ((size_t)(b * C_) + ctile * 128) * N_;
    const float* ag = g_A + ((size_t)b * K_) * N_;
    const int nb0 = ns * 512;

    const int xc = tid >> 1;      // c row 0..127 (x stage)
    const int xh = tid & 1;       // n-half (16 n)
    const int ak = tid >> 3;      // k row (A stage)
    const int aq = tid & 7;       // n quad

    float acc[2][2][4];
    #pragma unroll
    for (int mt = 0; mt < 2; mt++)
        #pragma unroll
        for (int ct = 0; ct < 2; ct++)
            #pragma unroll
            for (int j = 0; j < 4; j++) acc[mt][ct][j] = 0.f;

    // ---- prologue: async-issue chunks 0,1 ----
    #pragma unroll
    for (int s = 0; s < 2; s++) {
        const int nb = nb0 + s * 32;
        const uint32_t xdst = smb + s * 18432;
        #pragma unroll
        for (int j = 0; j < 4; j++)
            cpa16(xdst + (xc * 36 + xh * 16 + 4 * j) * 4,
                  xg + (size_t)xc * N_ + nb + xh * 16 + 4 * j);
        cpa16(smb + 55296 + s * 4608 + (ak * 36 + aq * 4) * 4,
              ag + (size_t)ak * N_ + nb + aq * 4);
        cpa_commit();
    }
    cpa_wait1();
    __syncthreads();

    // ---- mainloop: 16 chunks of 32 n ----
    for (int ch = 0; ch < 16; ch++) {
        if (ch < 14) {
            const int nb = nb0 + (ch + 2) * 32;
            const int st = (ch + 2) % 3;
            const uint32_t xdst = smb + st * 18432;
            #pragma unroll
            for (int j = 0; j < 4; j++)
                cpa16(xdst + (xc * 36 + xh * 16 + 4 * j) * 4,
                      xg + (size_t)xc * N_ + nb + xh * 16 + 4 * j);
            cpa16(smb + 55296 + st * 4608 + (ak * 36 + aq * 4) * 4,
                  ag + (size_t)ak * N_ + nb + aq * 4);
            cpa_commit();
        }
        const uint32_t* As = (const uint32_t*)(sm + 55296 + (ch % 3) * 4608);
        const uint32_t* Xs = (const uint32_t*)(sm + (ch % 3) * 18432);
        #pragma unroll
        for (int ks = 0; ks < 4; ks++) {
            const int nk = ks * 8;
            uint32_t af[2][4], bf[2][2];
            #pragma unroll
            for (int mt = 0; mt < 2; mt++) {
                const uint32_t* ap = As + (mt * 16 + ar0) * 36 + nk + an0;
                af[mt][0] = ap[0];                 // already tf32 bits
                af[mt][1] = ap[8 * 36];
                af[mt][2] = ap[4];
                af[mt][3] = ap[8 * 36 + 4];
            }
            #pragma unroll
            for (int ct = 0; ct < 2; ct++) {
                const uint32_t* bp = Xs + (cwarp + ct * 8 + ar0) * 36 + nk + an0;
                bf[ct][0] = tf32_of(__uint_as_float(bp[0]));
                bf[ct][1] = tf32_of(__uint_as_float(bp[4]));
            }
            #pragma unroll
            for (int mt = 0; mt < 2; mt++)
                #pragma unroll
                for (int ct = 0; ct < 2; ct++)
                    mma16888(acc[mt][ct], af[mt], bf[ct]);
        }
        if (ch < 14) cpa_wait1(); else cpa_wait0();
        __syncthreads();
    }

    // ---- epilogue -> g_part[b][ns][ctile][k][c] ----
    float* pb = g_part + (((size_t)(b * NS_ + ns) * CT_ + ctile) << 12);
    const int dr = lane >> 2;
    const int dc = (lane & 3) * 2;
    #pragma unroll
    for (int mt = 0; mt < 2; mt++) {
        #pragma unroll
        for (int ct = 0; ct < 2; ct++) {
            const int c0 = cwarp + ct * 8 + dc;
            const int r0 = mt * 16 + dr;
            *(float2*)(pb + r0 * 128 + c0) =
                make_float2(acc[mt][ct][0], acc[mt][ct][1]);
            *(float2*)(pb + (r0 + 8) * 128 + c0) =
                make_float2(acc[mt][ct][2], acc[mt][ct][3]);
        }
    }
}

// =====================================================================
// K4: per (b,k): Asum from g_as partials + combine + subtract Asum*cw.
// =====================================================================
__global__ void k4_final(float* __restrict__ out, const float* __restrict__ cw) {
    __shared__ float s_asum;
    const int bk  = blockIdx.x;
    const int b   = bk >> 5, k = bk & 31;
    const int tid = threadIdx.x;

    if (tid < 32) {
        float v = g_as[bk * NT_ + tid];
        #pragma unroll
        for (int o = 16; o; o >>= 1) v += __shfl_down_sync(0xffffffffu, v, o);
        if (tid == 0) s_asum = v;
    }
    __syncthreads();
    const float asum = s_asum;

    #pragma unroll
    for (int j = 0; j < 4; j++) {
        const int c  = tid + j * 128;
        const int ct = c >> 7, cl = c & 127;
        float v = 0.f;
        #pragma unroll
        for (int sp = 0; sp < NS_; sp++)
            v += g_part[(((size_t)(b * NS_ + sp) * CT_ + ct) << 12) + k * 128 + cl];
        out[(size_t)bk * C_ + c] = v - asum * cw[k * C_ + c];
    }
}

// =====================================================================
extern "C" void kernel_launch(void* const* d_in, const int* in_sizes, int n_in,
                              void* d_out, int out_size) {
    const float* x     = (const float*)d_in[0];
    const float* cw    = (const float*)d_in[1];
    const float* scale = (const float*)d_in[2];
    float* out = (float*)d_out;

    cudaFuncSetAttribute(k3_enc, cudaFuncAttributeMaxDynamicSharedMemorySize, K3_SMEM);

    k1_softmax<<<dim3(NT_, B_), 256>>>(x, cw, scale);
    k3_enc<<<dim3(CT_, NS_, B_), 256, K3_SMEM>>>(x);
    k4_final<<<B_ * K_, 128>>>(out, cw);
}

// round 16
// speedup vs baseline: 1.1043x; 1.0723x over previous
#include <cuda_runtime.h>
#include <cuda_fp16.h>
#include <cstdint>
#include <cstddef>

#define B_ 16
#define C_ 512
#define N_ 4096
#define K_ 32
#define NS_ 8                 // K3 n-splits (512 n each)
#define CT_ 4                 // K3 c-tiles (128 c each)
#define NT_ 32                // K1 n-tiles (128 n each)

// Scratch (device globals — allocation-free rule)
__device__ __half g_Ah[B_ * K_ * N_];                     // [b][k][n] fp16 A, 4 MB
__device__ float  g_part[B_ * NS_ * CT_ * K_ * 128];      // 8 MB partials
__device__ float  g_as[B_ * K_ * NT_];                    // per-ntile Asum partials

__device__ __forceinline__ uint32_t tf32_of(float a) {
    uint32_t r;
    asm("{ .reg .b32 t; cvt.rna.tf32.f32 t, %1; mov.b32 %0, t; }" : "=r"(r) : "f"(a));
    return r;
}
__device__ __forceinline__ void mma16888(float* d, const uint32_t* a, const uint32_t* b) {
    asm volatile(
        "mma.sync.aligned.m16n8k8.row.col.f32.tf32.tf32.f32 "
        "{%0,%1,%2,%3}, {%4,%5,%6,%7}, {%8,%9}, {%0,%1,%2,%3};"
        : "+f"(d[0]), "+f"(d[1]), "+f"(d[2]), "+f"(d[3])
        : "r"(a[0]), "r"(a[1]), "r"(a[2]), "r"(a[3]), "r"(b[0]), "r"(b[1]));
}
__device__ __forceinline__ void mma16816(float* d, const uint32_t* a, const uint32_t* b) {
    asm volatile(
        "mma.sync.aligned.m16n8k16.row.col.f32.f16.f16.f32 "
        "{%0,%1,%2,%3}, {%4,%5,%6,%7}, {%8,%9}, {%0,%1,%2,%3};"
        : "+f"(d[0]), "+f"(d[1]), "+f"(d[2]), "+f"(d[3])
        : "r"(a[0]), "r"(a[1]), "r"(a[2]), "r"(a[3]), "r"(b[0]), "r"(b[1]));
}
__device__ __forceinline__ uint32_t h2pack(float2 v) {   // lo half = v.x (lower k)
    uint32_t r;
    asm("cvt.rn.f16x2.f32 %0, %1, %2;" : "=r"(r) : "f"(v.y), "f"(v.x));
    return r;
}
__device__ __forceinline__ uint32_t smem_u32(const void* p) {
    uint32_t a;
    asm("{ .reg .u64 t; cvta.to.shared.u64 t, %1; cvt.u32.u64 %0, t; }" : "=r"(a) : "l"(p));
    return a;
}
__device__ __forceinline__ void cpa16(uint32_t dst, const void* src) {
    asm volatile("cp.async.cg.shared.global [%0], [%1], 16;" :: "r"(dst), "l"(src));
}
__device__ __forceinline__ void cpa_commit() {
    asm volatile("cp.async.commit_group;" ::: "memory");
}
__device__ __forceinline__ void cpa_wait1() {
    asm volatile("cp.async.wait_group 1;" ::: "memory");
}
__device__ __forceinline__ void cpa_wait0() {
    asm volatile("cp.async.wait_group 0;" ::: "memory");
}

// =====================================================================
// K1: logits + softmax via mma.sync tf32.  (R14/R15 config, 30.8us)
// Change vs R15: A emitted as fp16 to g_Ah (half the A-write traffic).
// grid (32 n-tiles, 16 b), 256 threads (8 warps, warp owns 16 n).
// =====================================================================
#define XS1 4352   // words per x stage (32 rows * 136)

__global__ void __launch_bounds__(256, 4) k1_softmax(const float* __restrict__ x,
                                                     const float* __restrict__ cw,
                                                     const float* __restrict__ scale) {
    __shared__ uint32_t ring[2 * XS1];        // 34816 B (aliased as Aoh after)
    __shared__ uint32_t cw_s[2 * 1152];       //  9216 B  [32k][36]
    __shared__ float sc_s[K_], c2_s[K_];
    __shared__ float as_s[8 * K_];

    const int tid  = threadIdx.x;
    const int lane = tid & 31, w = tid >> 5;
    const int b    = blockIdx.y;
    const int n0   = blockIdx.x * 128;
    const int ar0  = lane >> 2, an0 = lane & 3;
    const uint32_t smb = smem_u32(ring);

    if (tid < 32) sc_s[tid] = scale[tid];

    const int cst = tid >> 5;              // x: c sub-row 0..7 (rows cst+8j)
    const int nq4 = lane * 4;              // x: n offset
    const int kk  = tid >> 3;              // cw: k row
    const int cq  = tid & 7;               // cw: col quad

    const float* xg  = x  + (size_t)b * C_ * N_ + n0;
    const float* cwg = cw + kk * C_ + cq * 4;

    float c2p = 0.f;
    float sq0 = 0.f, sq1 = 0.f;
    float acc[4][4];
    #pragma unroll
    for (int nt = 0; nt < 4; nt++)
        #pragma unroll
        for (int j = 0; j < 4; j++) acc[nt][j] = 0.f;

    // ---- prologue ----
    #pragma unroll
    for (int j = 0; j < 4; j++)
        cpa16(smb + ((cst + 8 * j) * 136 + nq4) * 4,
              xg + (size_t)(cst + 8 * j) * N_ + nq4);
    cpa_commit();
    float4 cwr = *(const float4*)(cwg);
    {
        uint4 u = make_uint4(tf32_of(cwr.x), tf32_of(cwr.y), tf32_of(cwr.z), tf32_of(cwr.w));
        float t0 = __uint_as_float(u.x), t1 = __uint_as_float(u.y);
        float t2 = __uint_as_float(u.z), t3 = __uint_as_float(u.w);
        c2p += t0 * t0 + t1 * t1 + t2 * t2 + t3 * t3;
        *(uint4*)(cw_s + kk * 36 + cq * 4) = u;
    }
    cwr = *(const float4*)(cwg + 32);
    cpa_wait0();
    __syncthreads();

    // ---- mainloop: 16 chunks of 32 c ----
    for (int ch = 0; ch < 16; ch++) {
        if (ch < 15) {
            const uint32_t dstb = smb + ((ch + 1) & 1) * (XS1 * 4);
            #pragma unroll
            for (int j = 0; j < 4; j++)
                cpa16(dstb + ((cst + 8 * j) * 136 + nq4) * 4,
                      xg + (size_t)((ch + 1) * 32 + cst + 8 * j) * N_ + nq4);
            cpa_commit();
            uint4 u = make_uint4(tf32_of(cwr.x), tf32_of(cwr.y),
                                 tf32_of(cwr.z), tf32_of(cwr.w));
            float t0 = __uint_as_float(u.x), t1 = __uint_as_float(u.y);
            float t2 = __uint_as_float(u.z), t3 = __uint_as_float(u.w);
            c2p += t0 * t0 + t1 * t1 + t2 * t2 + t3 * t3;
            *(uint4*)(cw_s + ((ch + 1) & 1) * 1152 + kk * 36 + cq * 4) = u;
        }
        if (ch < 14) cwr = *(const float4*)(cwg + (ch + 2) * 32);

        const uint32_t* xb   = ring + (ch & 1) * XS1;
        const uint32_t* cb_s = cw_s + (ch & 1) * 1152;
        #pragma unroll
        for (int ks = 0; ks < 4; ks++) {
            const int cb = ks * 8;
            const uint32_t* ap = xb + (cb + an0) * 136 + 16 * w + ar0;
            const float f0 = __uint_as_float(ap[0]);
            const float f1 = __uint_as_float(ap[8]);
            const float f2 = __uint_as_float(ap[4 * 136]);
            const float f3 = __uint_as_float(ap[4 * 136 + 8]);
            sq0 += f0 * f0 + f2 * f2;
            sq1 += f1 * f1 + f3 * f3;
            uint32_t af[4];
            af[0] = tf32_of(f0); af[1] = tf32_of(f1);
            af[2] = tf32_of(f2); af[3] = tf32_of(f3);
            #pragma unroll
            for (int nt = 0; nt < 4; nt++) {
                uint32_t bf[2];
                const uint32_t* bp = cb_s + (8 * nt + ar0) * 36 + cb + an0;
                bf[0] = bp[0];
                bf[1] = bp[4];
                mma16888(acc[nt], af, bf);
            }
        }
        if (ch < 15) cpa_wait0();
        __syncthreads();
    }

    // ---- c2 reduce ----
    c2p += __shfl_down_sync(0xffffffffu, c2p, 4, 8);
    c2p += __shfl_down_sync(0xffffffffu, c2p, 2, 8);
    c2p += __shfl_down_sync(0xffffffffu, c2p, 1, 8);
    if (cq == 0) c2_s[kk] = c2p;
    __syncthreads();

    // ---- x2 via shfl over the an0 quad (exact fp32) ----
    float x2r0 = sq0, x2r1 = sq1;
    x2r0 += __shfl_xor_sync(0xffffffffu, x2r0, 1);
    x2r0 += __shfl_xor_sync(0xffffffffu, x2r0, 2);
    x2r1 += __shfl_xor_sync(0xffffffffu, x2r1, 1);
    x2r1 += __shfl_xor_sync(0xffffffffu, x2r1, 2);

    // ---- logits + softmax ----
    float lg0[8], lg1[8];
    float m0 = -1e30f, m1 = -1e30f;
    #pragma unroll
    for (int nt = 0; nt < 4; nt++) {
        #pragma unroll
        for (int j = 0; j < 2; j++) {
            const int k = 8 * nt + 2 * an0 + j;
            const float sck = sc_s[k], c2k = c2_s[k];
            float a = sck * (x2r0 - 2.f * acc[nt][j]     + c2k);
            float c = sck * (x2r1 - 2.f * acc[nt][2 + j] + c2k);
            lg0[nt * 2 + j] = a; lg1[nt * 2 + j] = c;
            m0 = fmaxf(m0, a); m1 = fmaxf(m1, c);
        }
    }
    m0 = fmaxf(m0, __shfl_xor_sync(0xffffffffu, m0, 1));
    m0 = fmaxf(m0, __shfl_xor_sync(0xffffffffu, m0, 2));
    m1 = fmaxf(m1, __shfl_xor_sync(0xffffffffu, m1, 1));
    m1 = fmaxf(m1, __shfl_xor_sync(0xffffffffu, m1, 2));
    float s0 = 0.f, s1 = 0.f;
    #pragma unroll
    for (int i = 0; i < 8; i++) {
        lg0[i] = __expf(lg0[i] - m0); s0 += lg0[i];
        lg1[i] = __expf(lg1[i] - m1); s1 += lg1[i];
    }
    s0 += __shfl_xor_sync(0xffffffffu, s0, 1);
    s0 += __shfl_xor_sync(0xffffffffu, s0, 2);
    s1 += __shfl_xor_sync(0xffffffffu, s1, 1);
    s1 += __shfl_xor_sync(0xffffffffu, s1, 2);
    const float inv0 = 1.f / s0, inv1 = 1.f / s1;

    // ---- Asum partials (exact fp32) ----
    float akp[8];
    #pragma unroll
    for (int i = 0; i < 8; i++) akp[i] = lg0[i] * inv0 + lg1[i] * inv1;
    #pragma unroll
    for (int off = 4; off < 32; off <<= 1)
        #pragma unroll
        for (int i = 0; i < 8; i++)
            akp[i] += __shfl_xor_sync(0xffffffffu, akp[i], off);
    if (ar0 == 0) {
        #pragma unroll
        for (int nt = 0; nt < 4; nt++)
            #pragma unroll
            for (int j = 0; j < 2; j++)
                as_s[w * 32 + 8 * nt + 2 * an0 + j] = akp[nt * 2 + j];
    }

    // ---- A (fp16) -> smem transpose (alias ring) -> coalesced STG ----
    __half* Aoh = (__half*)ring;                  // [32 k][136 n-pad], 8704 B
    #pragma unroll
    for (int nt = 0; nt < 4; nt++) {
        #pragma unroll
        for (int j = 0; j < 2; j++) {
            const int k = 8 * nt + 2 * an0 + j;
            Aoh[k * 136 + 16 * w + ar0]     = __float2half_rn(lg0[nt * 2 + j] * inv0);
            Aoh[k * 136 + 16 * w + ar0 + 8] = __float2half_rn(lg1[nt * 2 + j] * inv1);
        }
    }
    __syncthreads();
    if (tid < 32) {
        float s = 0.f;
        #pragma unroll
        for (int ww = 0; ww < 8; ww++) s += as_s[ww * 32 + tid];
        g_as[(b * K_ + tid) * NT_ + blockIdx.x] = s;
    }
    __half* ag = g_Ah + (size_t)(b * K_) * N_ + n0;
    #pragma unroll
    for (int t = 0; t < 2; t++) {
        int f = tid + t * 256;                    // 0..511
        int k = f >> 4, q = f & 15;               // 16 uint4 per k row
        *(uint4*)(ag + (size_t)k * N_ + q * 8) = *(uint4*)(Aoh + k * 136 + q * 8);
    }
}

// =====================================================================
// K3: enc partial via mma.sync fp16 m16n8k16.
// D[32k x 128c] += sum_n A[k,n] * x[c,n] over 512 n per CTA.
// 32-n chunks (16 iters), 3-stage cp.async rings:
//   x fp32 [128c][40-pad] 20480 B/stage (pad 40 => conflict-free LDS.64)
//   A fp16 [32k][20-pad words] 2560 B/stage
// dyn smem 69120 B -> 3 CTAs/SM, depth-2 prefetch.
// Inner loop per chunk: 8 MMA + 16 LDS.32 + 8 LDS.64 + 8 CVT.
// =====================================================================
#define K3_SMEM 69120

__global__ void __launch_bounds__(256) k3_enc(const float* __restrict__ x) {
    extern __shared__ char sm[];
    const uint32_t smb = smem_u32(sm);

    const int tid   = threadIdx.x;
    const int lane  = tid & 31, w = tid >> 5;
    const int ctile = blockIdx.x;
    const int ns    = blockIdx.y;
    const int b     = blockIdx.z;
    const int cwarp = w * 16;
    const int ar0   = lane >> 2, an0 = lane & 3;

    const float*  xg = x    + ((size_t)(b * C_) + ctile * 128) * N_;
    const __half* ag = g_Ah + ((size_t)b * K_) * N_;
    const int nb0 = ns * 512;

    const int xc   = tid >> 1;      // c row 0..127 (x stage)
    const int xh   = tid & 1;       // n-half (16 n)
    const int arow = tid >> 2;      // A: k row (tid<128)
    const int aseg = tid & 3;       // A: 16B segment (8 halves)

    float acc[2][2][4];
    #pragma unroll
    for (int mt = 0; mt < 2; mt++)
        #pragma unroll
        for (int ct = 0; ct < 2; ct++)
            #pragma unroll
            for (int j = 0; j < 4; j++) acc[mt][ct][j] = 0.f;

    // ---- prologue: async-issue chunks 0,1 ----
    #pragma unroll
    for (int s = 0; s < 2; s++) {
        const int nb = nb0 + s * 32;
        const uint32_t xdst = smb + s * 20480;
        #pragma unroll
        for (int j = 0; j < 4; j++)
            cpa16(xdst + (xc * 40 + xh * 16 + 4 * j) * 4,
                  xg + (size_t)xc * N_ + nb + xh * 16 + 4 * j);
        if (tid < 128)
            cpa16(smb + 61440 + s * 2560 + (arow * 20 + aseg * 4) * 4,
                  ag + (size_t)arow * N_ + nb + aseg * 8);
        cpa_commit();
    }
    cpa_wait1();
    __syncthreads();

    // ---- mainloop: 16 chunks of 32 n ----
    for (int ch = 0; ch < 16; ch++) {
        if (ch < 14) {
            const int nb = nb0 + (ch + 2) * 32;
            const int st = (ch + 2) % 3;
            const uint32_t xdst = smb + st * 20480;
            #pragma unroll
            for (int j = 0; j < 4; j++)
                cpa16(xdst + (xc * 40 + xh * 16 + 4 * j) * 4,
                      xg + (size_t)xc * N_ + nb + xh * 16 + 4 * j);
            if (tid < 128)
                cpa16(smb + 61440 + st * 2560 + (arow * 20 + aseg * 4) * 4,
                      ag + (size_t)arow * N_ + nb + aseg * 8);
            cpa_commit();
        }
        const uint32_t* As = (const uint32_t*)(sm + 61440 + (ch % 3) * 2560);
        const float*    Xs = (const float*)(sm + (ch % 3) * 20480);
        #pragma unroll
        for (int ks = 0; ks < 2; ks++) {
            const int o = ks * 8 + an0;          // A word offset within row
            uint32_t af[2][4];
            #pragma unroll
            for (int mt = 0; mt < 2; mt++) {
                const uint32_t* ap = As + (mt * 16 + ar0) * 20 + o;
                af[mt][0] = ap[0];
                af[mt][1] = ap[8 * 20];
                af[mt][2] = ap[4];
                af[mt][3] = ap[8 * 20 + 4];
            }
            uint32_t bf[2][2];
            #pragma unroll
            for (int ct = 0; ct < 2; ct++) {
                const float* bp = Xs + (cwarp + ct * 8 + ar0) * 40 + ks * 16 + 2 * an0;
                bf[ct][0] = h2pack(*(const float2*)bp);
                bf[ct][1] = h2pack(*(const float2*)(bp + 8));
            }
            #pragma unroll
            for (int mt = 0; mt < 2; mt++)
                #pragma unroll
                for (int ct = 0; ct < 2; ct++)
                    mma16816(acc[mt][ct], af[mt], bf[ct]);
        }
        if (ch < 14) cpa_wait1(); else cpa_wait0();
        __syncthreads();
    }

    // ---- epilogue -> g_part[b][ns][ctile][k][c] ----
    float* pb = g_part + (((size_t)(b * NS_ + ns) * CT_ + ctile) << 12);
    const int dr = lane >> 2;
    const int dc = (lane & 3) * 2;
    #pragma unroll
    for (int mt = 0; mt < 2; mt++) {
        #pragma unroll
        for (int ct = 0; ct < 2; ct++) {
            const int c0 = cwarp + ct * 8 + dc;
            const int r0 = mt * 16 + dr;
            *(float2*)(pb + r0 * 128 + c0) =
                make_float2(acc[mt][ct][0], acc[mt][ct][1]);
            *(float2*)(pb + (r0 + 8) * 128 + c0) =
                make_float2(acc[mt][ct][2], acc[mt][ct][3]);
        }
    }
}

// =====================================================================
// K4: per (b,k): Asum from g_as partials + combine + subtract Asum*cw.
// =====================================================================
__global__ void k4_final(float* __restrict__ out, const float* __restrict__ cw) {
    __shared__ float s_asum;
    const int bk  = blockIdx.x;
    const int b   = bk >> 5, k = bk & 31;
    const int tid = threadIdx.x;

    if (tid < 32) {
        float v = g_as[bk * NT_ + tid];
        #pragma unroll
        for (int o = 16; o; o >>= 1) v += __shfl_down_sync(0xffffffffu, v, o);
        if (tid == 0) s_asum = v;
    }
    __syncthreads();
    const float asum = s_asum;

    #pragma unroll
    for (int j = 0; j < 4; j++) {
        const int c  = tid + j * 128;
        const int ct = c >> 7, cl = c & 127;
        float v = 0.f;
        #pragma unroll
        for (int sp = 0; sp < NS_; sp++)
            v += g_part[(((size_t)(b * NS_ + sp) * CT_ + ct) << 12) + k * 128 + cl];
        out[(size_t)bk * C_ + c] = v - asum * cw[k * C_ + c];
    }
}

// =====================================================================
extern "C" void kernel_launch(void* const* d_in, const int* in_sizes, int n_in,
                              void* d_out, int out_size) {
    const float* x     = (const float*)d_in[0];
    const float* cw    = (const float*)d_in[1];
    const float* scale = (const float*)d_in[2];
    float* out = (float*)d_out;

    cudaFuncSetAttribute(k3_enc, cudaFuncAttributeMaxDynamicSharedMemorySize, K3_SMEM);

    k1_softmax<<<dim3(NT_, B_), 256>>>(x, cw, scale);
    k3_enc<<<dim3(CT_, NS_, B_), 256, K3_SMEM>>>(x);
    k4_final<<<B_ * K_, 128>>>(out, cw);
}

// round 17
// speedup vs baseline: 1.2606x; 1.1416x over previous
#include <cuda_runtime.h>
#include <cuda_fp16.h>
#include <cstdint>
#include <cstddef>

#define B_ 16
#define C_ 512
#define N_ 4096
#define K_ 32
#define NS_ 8                 // K3 n-splits (512 n each)
#define CT_ 4                 // K3 c-tiles (128 c each)
#define NT_ 32                // K1 n-tiles (128 n each)

// Scratch (device globals — allocation-free rule)
__device__ __half g_Ah[B_ * K_ * N_];                     // [b][k][n] fp16 A, 4 MB
__device__ float  g_part[B_ * NS_ * CT_ * K_ * 128];      // 8 MB partials
__device__ float  g_as[B_ * K_ * NT_];                    // per-ntile Asum partials

__device__ __forceinline__ uint32_t tf32_of(float a) {
    uint32_t r;
    asm("{ .reg .b32 t; cvt.rna.tf32.f32 t, %1; mov.b32 %0, t; }" : "=r"(r) : "f"(a));
    return r;
}
__device__ __forceinline__ void mma16888(float* d, const uint32_t* a, const uint32_t* b) {
    asm volatile(
        "mma.sync.aligned.m16n8k8.row.col.f32.tf32.tf32.f32 "
        "{%0,%1,%2,%3}, {%4,%5,%6,%7}, {%8,%9}, {%0,%1,%2,%3};"
        : "+f"(d[0]), "+f"(d[1]), "+f"(d[2]), "+f"(d[3])
        : "r"(a[0]), "r"(a[1]), "r"(a[2]), "r"(a[3]), "r"(b[0]), "r"(b[1]));
}
__device__ __forceinline__ void mma16816(float* d, const uint32_t* a, const uint32_t* b) {
    asm volatile(
        "mma.sync.aligned.m16n8k16.row.col.f32.f16.f16.f32 "
        "{%0,%1,%2,%3}, {%4,%5,%6,%7}, {%8,%9}, {%0,%1,%2,%3};"
        : "+f"(d[0]), "+f"(d[1]), "+f"(d[2]), "+f"(d[3])
        : "r"(a[0]), "r"(a[1]), "r"(a[2]), "r"(a[3]), "r"(b[0]), "r"(b[1]));
}
__device__ __forceinline__ uint32_t h2pack(float2 v) {   // lo half = v.x (lower k)
    uint32_t r;
    asm("cvt.rn.f16x2.f32 %0, %1, %2;" : "=r"(r) : "f"(v.y), "f"(v.x));
    return r;
}
__device__ __forceinline__ uint32_t smem_u32(const void* p) {
    uint32_t a;
    asm("{ .reg .u64 t; cvta.to.shared.u64 t, %1; cvt.u32.u64 %0, t; }" : "=r"(a) : "l"(p));
    return a;
}
__device__ __forceinline__ void cpa16(uint32_t dst, const void* src) {
    asm volatile("cp.async.cg.shared.global [%0], [%1], 16;" :: "r"(dst), "l"(src));
}
__device__ __forceinline__ void cpa_commit() {
    asm volatile("cp.async.commit_group;" ::: "memory");
}
__device__ __forceinline__ void cpa_wait1() {
    asm volatile("cp.async.wait_group 1;" ::: "memory");
}
__device__ __forceinline__ void cpa_wait0() {
    asm volatile("cp.async.wait_group 0;" ::: "memory");
}

// =====================================================================
// K1: logits + softmax via mma.sync tf32.  (R15/R16 config — at BW floor)
// grid (32 n-tiles, 16 b), 256 threads (8 warps, warp owns 16 n).
// =====================================================================
#define XS1 4352   // words per x stage (32 rows * 136)

__global__ void __launch_bounds__(256, 4) k1_softmax(const float* __restrict__ x,
                                                     const float* __restrict__ cw,
                                                     const float* __restrict__ scale) {
    __shared__ uint32_t ring[2 * XS1];        // 34816 B (aliased as Aoh after)
    __shared__ uint32_t cw_s[2 * 1152];       //  9216 B  [32k][36]
    __shared__ float sc_s[K_], c2_s[K_];
    __shared__ float as_s[8 * K_];

    const int tid  = threadIdx.x;
    const int lane = tid & 31, w = tid >> 5;
    const int b    = blockIdx.y;
    const int n0   = blockIdx.x * 128;
    const int ar0  = lane >> 2, an0 = lane & 3;
    const uint32_t smb = smem_u32(ring);

    if (tid < 32) sc_s[tid] = scale[tid];

    const int cst = tid >> 5;              // x: c sub-row 0..7 (rows cst+8j)
    const int nq4 = lane * 4;              // x: n offset
    const int kk  = tid >> 3;              // cw: k row
    const int cq  = tid & 7;               // cw: col quad

    const float* xg  = x  + (size_t)b * C_ * N_ + n0;
    const float* cwg = cw + kk * C_ + cq * 4;

    float c2p = 0.f;
    float sq0 = 0.f, sq1 = 0.f;
    float acc[4][4];
    #pragma unroll
    for (int nt = 0; nt < 4; nt++)
        #pragma unroll
        for (int j = 0; j < 4; j++) acc[nt][j] = 0.f;

    // ---- prologue ----
    #pragma unroll
    for (int j = 0; j < 4; j++)
        cpa16(smb + ((cst + 8 * j) * 136 + nq4) * 4,
              xg + (size_t)(cst + 8 * j) * N_ + nq4);
    cpa_commit();
    float4 cwr = *(const float4*)(cwg);
    {
        uint4 u = make_uint4(tf32_of(cwr.x), tf32_of(cwr.y), tf32_of(cwr.z), tf32_of(cwr.w));
        float t0 = __uint_as_float(u.x), t1 = __uint_as_float(u.y);
        float t2 = __uint_as_float(u.z), t3 = __uint_as_float(u.w);
        c2p += t0 * t0 + t1 * t1 + t2 * t2 + t3 * t3;
        *(uint4*)(cw_s + kk * 36 + cq * 4) = u;
    }
    cwr = *(const float4*)(cwg + 32);
    cpa_wait0();
    __syncthreads();

    // ---- mainloop: 16 chunks of 32 c ----
    for (int ch = 0; ch < 16; ch++) {
        if (ch < 15) {
            const uint32_t dstb = smb + ((ch + 1) & 1) * (XS1 * 4);
            #pragma unroll
            for (int j = 0; j < 4; j++)
                cpa16(dstb + ((cst + 8 * j) * 136 + nq4) * 4,
                      xg + (size_t)((ch + 1) * 32 + cst + 8 * j) * N_ + nq4);
            cpa_commit();
            uint4 u = make_uint4(tf32_of(cwr.x), tf32_of(cwr.y),
                                 tf32_of(cwr.z), tf32_of(cwr.w));
            float t0 = __uint_as_float(u.x), t1 = __uint_as_float(u.y);
            float t2 = __uint_as_float(u.z), t3 = __uint_as_float(u.w);
            c2p += t0 * t0 + t1 * t1 + t2 * t2 + t3 * t3;
            *(uint4*)(cw_s + ((ch + 1) & 1) * 1152 + kk * 36 + cq * 4) = u;
        }
        if (ch < 14) cwr = *(const float4*)(cwg + (ch + 2) * 32);

        const uint32_t* xb   = ring + (ch & 1) * XS1;
        const uint32_t* cb_s = cw_s + (ch & 1) * 1152;
        #pragma unroll
        for (int ks = 0; ks < 4; ks++) {
            const int cb = ks * 8;
            const uint32_t* ap = xb + (cb + an0) * 136 + 16 * w + ar0;
            const float f0 = __uint_as_float(ap[0]);
            const float f1 = __uint_as_float(ap[8]);
            const float f2 = __uint_as_float(ap[4 * 136]);
            const float f3 = __uint_as_float(ap[4 * 136 + 8]);
            sq0 += f0 * f0 + f2 * f2;
            sq1 += f1 * f1 + f3 * f3;
            uint32_t af[4];
            af[0] = tf32_of(f0); af[1] = tf32_of(f1);
            af[2] = tf32_of(f2); af[3] = tf32_of(f3);
            #pragma unroll
            for (int nt = 0; nt < 4; nt++) {
                uint32_t bf[2];
                const uint32_t* bp = cb_s + (8 * nt + ar0) * 36 + cb + an0;
                bf[0] = bp[0];
                bf[1] = bp[4];
                mma16888(acc[nt], af, bf);
            }
        }
        if (ch < 15) cpa_wait0();
        __syncthreads();
    }

    // ---- c2 reduce ----
    c2p += __shfl_down_sync(0xffffffffu, c2p, 4, 8);
    c2p += __shfl_down_sync(0xffffffffu, c2p, 2, 8);
    c2p += __shfl_down_sync(0xffffffffu, c2p, 1, 8);
    if (cq == 0) c2_s[kk] = c2p;
    __syncthreads();

    // ---- x2 via shfl over the an0 quad (exact fp32) ----
    float x2r0 = sq0, x2r1 = sq1;
    x2r0 += __shfl_xor_sync(0xffffffffu, x2r0, 1);
    x2r0 += __shfl_xor_sync(0xffffffffu, x2r0, 2);
    x2r1 += __shfl_xor_sync(0xffffffffu, x2r1, 1);
    x2r1 += __shfl_xor_sync(0xffffffffu, x2r1, 2);

    // ---- logits + softmax ----
    float lg0[8], lg1[8];
    float m0 = -1e30f, m1 = -1e30f;
    #pragma unroll
    for (int nt = 0; nt < 4; nt++) {
        #pragma unroll
        for (int j = 0; j < 2; j++) {
            const int k = 8 * nt + 2 * an0 + j;
            const float sck = sc_s[k], c2k = c2_s[k];
            float a = sck * (x2r0 - 2.f * acc[nt][j]     + c2k);
            float c = sck * (x2r1 - 2.f * acc[nt][2 + j] + c2k);
            lg0[nt * 2 + j] = a; lg1[nt * 2 + j] = c;
            m0 = fmaxf(m0, a); m1 = fmaxf(m1, c);
        }
    }
    m0 = fmaxf(m0, __shfl_xor_sync(0xffffffffu, m0, 1));
    m0 = fmaxf(m0, __shfl_xor_sync(0xffffffffu, m0, 2));
    m1 = fmaxf(m1, __shfl_xor_sync(0xffffffffu, m1, 1));
    m1 = fmaxf(m1, __shfl_xor_sync(0xffffffffu, m1, 2));
    float s0 = 0.f, s1 = 0.f;
    #pragma unroll
    for (int i = 0; i < 8; i++) {
        lg0[i] = __expf(lg0[i] - m0); s0 += lg0[i];
        lg1[i] = __expf(lg1[i] - m1); s1 += lg1[i];
    }
    s0 += __shfl_xor_sync(0xffffffffu, s0, 1);
    s0 += __shfl_xor_sync(0xffffffffu, s0, 2);
    s1 += __shfl_xor_sync(0xffffffffu, s1, 1);
    s1 += __shfl_xor_sync(0xffffffffu, s1, 2);
    const float inv0 = 1.f / s0, inv1 = 1.f / s1;

    // ---- Asum partials (exact fp32) ----
    float akp[8];
    #pragma unroll
    for (int i = 0; i < 8; i++) akp[i] = lg0[i] * inv0 + lg1[i] * inv1;
    #pragma unroll
    for (int off = 4; off < 32; off <<= 1)
        #pragma unroll
        for (int i = 0; i < 8; i++)
            akp[i] += __shfl_xor_sync(0xffffffffu, akp[i], off);
    if (ar0 == 0) {
        #pragma unroll
        for (int nt = 0; nt < 4; nt++)
            #pragma unroll
            for (int j = 0; j < 2; j++)
                as_s[w * 32 + 8 * nt + 2 * an0 + j] = akp[nt * 2 + j];
    }

    // ---- A (fp16) -> smem transpose (alias ring) -> coalesced STG ----
    __half* Aoh = (__half*)ring;                  // [32 k][136 n-pad]
    #pragma unroll
    for (int nt = 0; nt < 4; nt++) {
        #pragma unroll
        for (int j = 0; j < 2; j++) {
            const int k = 8 * nt + 2 * an0 + j;
            Aoh[k * 136 + 16 * w + ar0]     = __float2half_rn(lg0[nt * 2 + j] * inv0);
            Aoh[k * 136 + 16 * w + ar0 + 8] = __float2half_rn(lg1[nt * 2 + j] * inv1);
        }
    }
    __syncthreads();
    if (tid < 32) {
        float s = 0.f;
        #pragma unroll
        for (int ww = 0; ww < 8; ww++) s += as_s[ww * 32 + tid];
        g_as[(b * K_ + tid) * NT_ + blockIdx.x] = s;
    }
    __half* ag = g_Ah + (size_t)(b * K_) * N_ + n0;
    #pragma unroll
    for (int t = 0; t < 2; t++) {
        int f = tid + t * 256;                    // 0..511
        int k = f >> 4, q = f & 15;               // 16 uint4 per k row
        *(uint4*)(ag + (size_t)k * N_ + q * 8) = *(uint4*)(Aoh + k * 136 + q * 8);
    }
}

// =====================================================================
// K3: enc partial via mma.sync fp16 m16n8k16.
// R17: XOR-swizzled x stages (128 rows x 32 words, no pad) -> 16KB/stage;
// 3-stage x + 3-stage A = 56832 B dyn smem -> 4 CTAs/SM with depth-2.
// Swizzle: W' = ((W>>3) ^ (c&3))<<3 | (W&7)  (8-word superblocks).
// D[32k x 128c] += sum_n A[k,n] * x[c,n] over 512 n per CTA.
// =====================================================================
#define K3_SMEM 56832
#define XW3 4096   // words per x stage (128 rows * 32)

__global__ void __launch_bounds__(256, 4) k3_enc(const float* __restrict__ x) {
    extern __shared__ char sm[];
    const uint32_t smb = smem_u32(sm);

    const int tid   = threadIdx.x;
    const int lane  = tid & 31, w = tid >> 5;
    const int ctile = blockIdx.x;
    const int ns    = blockIdx.y;
    const int b     = blockIdx.z;
    const int cwarp = w * 16;
    const int ar0   = lane >> 2, an0 = lane & 3;

    const float*  xg = x    + ((size_t)(b * C_) + ctile * 128) * N_;
    const __half* ag = g_Ah + ((size_t)b * K_) * N_;
    const int nb0 = ns * 512;

    const int xc   = tid >> 1;      // c row 0..127 (x stage)
    const int xh   = tid & 1;       // n-half (16 n)
    const int xcs  = xc & 3;        // swizzle key
    const int arow = tid >> 2;      // A: k row (tid<128)
    const int aseg = tid & 3;       // A: 16B segment

    float acc[2][2][4];
    #pragma unroll
    for (int mt = 0; mt < 2; mt++)
        #pragma unroll
        for (int ct = 0; ct < 2; ct++)
            #pragma unroll
            for (int j = 0; j < 4; j++) acc[mt][ct][j] = 0.f;

    // ---- prologue: async-issue chunks 0,1 ----
    #pragma unroll
    for (int s = 0; s < 2; s++) {
        const int nb = nb0 + s * 32;
        const uint32_t xdst = smb + s * (XW3 * 4);
        #pragma unroll
        for (int j = 0; j < 4; j++) {
            const int sb  = xh * 2 + (j >> 1);
            const int dstw = xc * 32 + ((sb ^ xcs) << 3) + 4 * (j & 1);
            cpa16(xdst + dstw * 4, xg + (size_t)xc * N_ + nb + xh * 16 + 4 * j);
        }
        if (tid < 128)
            cpa16(smb + 3 * (XW3 * 4) + s * 2560 + (arow * 20 + aseg * 4) * 4,
                  ag + (size_t)arow * N_ + nb + aseg * 8);
        cpa_commit();
    }
    cpa_wait1();
    __syncthreads();

    // ---- mainloop: 16 chunks of 32 n ----
    for (int ch = 0; ch < 16; ch++) {
        if (ch < 14) {
            const int nb = nb0 + (ch + 2) * 32;
            const int st = (ch + 2) % 3;
            const uint32_t xdst = smb + st * (XW3 * 4);
            #pragma unroll
            for (int j = 0; j < 4; j++) {
                const int sb  = xh * 2 + (j >> 1);
                const int dstw = xc * 32 + ((sb ^ xcs) << 3) + 4 * (j & 1);
                cpa16(xdst + dstw * 4, xg + (size_t)xc * N_ + nb + xh * 16 + 4 * j);
            }
            if (tid < 128)
                cpa16(smb + 3 * (XW3 * 4) + st * 2560 + (arow * 20 + aseg * 4) * 4,
                      ag + (size_t)arow * N_ + nb + aseg * 8);
            cpa_commit();
        }
        const uint32_t* As = (const uint32_t*)(sm + 3 * (XW3 * 4) + (ch % 3) * 2560);
        const float*    Xs = (const float*)(sm + (ch % 3) * (XW3 * 4));
        #pragma unroll
        for (int ks = 0; ks < 2; ks++) {
            const int o = ks * 8 + an0;          // A word offset within row
            uint32_t af[2][4];
            #pragma unroll
            for (int mt = 0; mt < 2; mt++) {
                const uint32_t* ap = As + (mt * 16 + ar0) * 20 + o;
                af[mt][0] = ap[0];
                af[mt][1] = ap[8 * 20];
                af[mt][2] = ap[4];
                af[mt][3] = ap[8 * 20 + 4];
            }
            uint32_t bf[2][2];
            const int sw = ar0 & 3;              // c&3 for this lane's rows
            const int w0 = (((ks * 2)     ^ sw) << 3) + 2 * an0;
            const int w1 = (((ks * 2 + 1) ^ sw) << 3) + 2 * an0;
            #pragma unroll
            for (int ct = 0; ct < 2; ct++) {
                const float* bp = Xs + (cwarp + ct * 8 + ar0) * 32;
                bf[ct][0] = h2pack(*(const float2*)(bp + w0));
                bf[ct][1] = h2pack(*(const float2*)(bp + w1));
            }
            #pragma unroll
            for (int mt = 0; mt < 2; mt++)
                #pragma unroll
                for (int ct = 0; ct < 2; ct++)
                    mma16816(acc[mt][ct], af[mt], bf[ct]);
        }
        if (ch < 14) cpa_wait1(); else cpa_wait0();
        __syncthreads();
    }

    // ---- epilogue -> g_part[b][ns][ctile][k][c] ----
    float* pb = g_part + (((size_t)(b * NS_ + ns) * CT_ + ctile) << 12);
    const int dr = lane >> 2;
    const int dc = (lane & 3) * 2;
    #pragma unroll
    for (int mt = 0; mt < 2; mt++) {
        #pragma unroll
        for (int ct = 0; ct < 2; ct++) {
            const int c0 = cwarp + ct * 8 + dc;
            const int r0 = mt * 16 + dr;
            *(float2*)(pb + r0 * 128 + c0) =
                make_float2(acc[mt][ct][0], acc[mt][ct][1]);
            *(float2*)(pb + (r0 + 8) * 128 + c0) =
                make_float2(acc[mt][ct][2], acc[mt][ct][3]);
        }
    }
}

// =====================================================================
// K4: per (b,k): Asum from g_as partials + combine + subtract Asum*cw.
// =====================================================================
__global__ void k4_final(float* __restrict__ out, const float* __restrict__ cw) {
    __shared__ float s_asum;
    const int bk  = blockIdx.x;
    const int b   = bk >> 5, k = bk & 31;
    const int tid = threadIdx.x;

    if (tid < 32) {
        float v = g_as[bk * NT_ + tid];
        #pragma unroll
        for (int o = 16; o; o >>= 1) v += __shfl_down_sync(0xffffffffu, v, o);
        if (tid == 0) s_asum = v;
    }
    __syncthreads();
    const float asum = s_asum;

    #pragma unroll
    for (int j = 0; j < 4; j++) {
        const int c  = tid + j * 128;
        const int ct = c >> 7, cl = c & 127;
        float v = 0.f;
        #pragma unroll
        for (int sp = 0; sp < NS_; sp++)
            v += g_part[(((size_t)(b * NS_ + sp) * CT_ + ct) << 12) + k * 128 + cl];
        out[(size_t)bk * C_ + c] = v - asum * cw[k * C_ + c];
    }
}

// =====================================================================
extern "C" void kernel_launch(void* const* d_in, const int* in_sizes, int n_in,
                              void* d_out, int out_size) {
    const float* x     = (const float*)d_in[0];
    const float* cw    = (const float*)d_in[1];
    const float* scale = (const float*)d_in[2];
    float* out = (float*)d_out;

    cudaFuncSetAttribute(k3_enc, cudaFuncAttributeMaxDynamicSharedMemorySize, K3_SMEM);

    k1_softmax<<<dim3(NT_, B_), 256>>>(x, cw, scale);
    k3_enc<<<dim3(CT_, NS_, B_), 256, K3_SMEM>>>(x);
    k4_final<<<B_ * K_, 128>>>(out, cw);
}